// round 2
// baseline (speedup 1.0000x reference)
#include <cuda_runtime.h>
#include <math.h>

#define B_    8
#define T_    8
#define C_    256
#define CH_   64
#define Wd    56
#define HW_   3136
#define PT    128
#define NPB   25          // ceil(HW_/PT)

typedef unsigned long long ull;

// ---------------- scratch (device globals; no allocation allowed) ----------------
__device__ float g_maxavg[(size_t)B_ * T_ * 2 * HW_];
__device__ float g_gate[(size_t)B_ * T_ * HW_];
__device__ float g_wr[C_ * 3 * CH_];                    // [(c*3+dt)*64+ch]  (flat = c*192 + dt*64 + ch)
__device__ float g_we[CH_ * C_];                        // [cin*256+cout]
__device__ float g_t[(size_t)B_ * CH_ * T_ * HW_];      // (B,64,T,HW)
__device__ float g_xt[(size_t)B_ * C_ * T_ * HW_];      // (B,C,T,HW)
__device__ float g_vpart[(size_t)B_ * C_ * T_ * NPB];
__device__ float g_kern[B_ * C_ * 3];

// ---------------- f32x2 helpers ----------------
__device__ __forceinline__ void ffma2(ull& d, ull a, ull b) {
    asm("fma.rn.f32x2 %0, %1, %2, %0;" : "+l"(d) : "l"(a), "l"(b));
}
__device__ __forceinline__ ull packdup(float w) {
    ull u; asm("mov.b64 %0, {%1, %1};" : "=l"(u) : "f"(w)); return u;
}
__device__ __forceinline__ float2 unpk(ull u) {
    float2 f; asm("mov.b64 {%0, %1}, %2;" : "=f"(f.x), "=f"(f.y) : "l"(u)); return f;
}

// ---------------- prep: transpose weights ----------------
__global__ void k_prep(const float* __restrict__ wr, const float* __restrict__ we) {
    int idx = blockIdx.x * blockDim.x + threadIdx.x;
    if (idx < C_ * 3 * CH_) {
        int ch = idx & 63;
        int dtc = idx >> 6;
        int c = dtc / 3, dt = dtc % 3;
        g_wr[idx] = wr[ch * (C_ * 3) + c * 3 + dt];
    }
    if (idx < CH_ * C_) {
        int cout = idx & 255;
        int cin = idx >> 8;
        g_we[idx] = we[cout * CH_ + cin];
    }
}

// ---------------- channel max/mean ----------------
__global__ __launch_bounds__(256) void k_maxmean(const float* __restrict__ x) {
    int bt = blockIdx.y;
    int p = blockIdx.x * blockDim.x + threadIdx.x;
    if (p >= HW_) return;
    const float* xp = x + (size_t)bt * C_ * HW_ + p;
    float mx = -INFINITY, sm = 0.f;
#pragma unroll 4
    for (int c = 0; c < C_; c++) {
        float v = xp[(size_t)c * HW_];
        mx = fmaxf(mx, v);
        sm += v;
    }
    g_maxavg[(size_t)bt * 2 * HW_ + p] = mx;
    g_maxavg[(size_t)bt * 2 * HW_ + HW_ + p] = sm * (1.f / C_);
}

// ---------------- 7x7 conv -> spatial gate ----------------
__global__ __launch_bounds__(256) void k_spatial(const float* __restrict__ w) {
    __shared__ float sw[98];
    int tid = threadIdx.x;
    if (tid < 98) sw[tid] = w[tid];
    __syncthreads();
    int bt = blockIdx.y;
    int p = blockIdx.x * blockDim.x + tid;
    if (p >= HW_) return;
    int py = p / Wd, px = p % Wd;
    const float* mb = g_maxavg + (size_t)bt * 2 * HW_;
    float s = 0.f;
#pragma unroll
    for (int ky = 0; ky < 7; ky++) {
        int iy = py + ky - 3;
        if (iy < 0 || iy >= Wd) continue;
#pragma unroll
        for (int kx = 0; kx < 7; kx++) {
            int ix = px + kx - 3;
            if (ix < 0 || ix >= Wd) continue;
            float m = mb[iy * Wd + ix];
            float a = mb[HW_ + iy * Wd + ix];
            s += sw[ky * 7 + kx] * m + sw[49 + ky * 7 + kx] * a;
        }
    }
    g_gate[(size_t)bt * HW_ + p] = 1.f + 1.f / (1.f + __expf(-s));
}

// ---------------- fused gated reduce conv3d GEMM (64 x PT, K=768) + BN + relu ----------------
// 256 thr = 16(ty:ch)x16(tx:px); thread tile 4ch x 8px; f32x2-packed over px pairs.
__global__ __launch_bounds__(256, 2) void k_reduce(
    const float* __restrict__ x, const float* __restrict__ gamma,
    const float* __restrict__ beta, const float* __restrict__ mean,
    const float* __restrict__ var) {
    __shared__ __align__(16) float sgate[3][PT];
    __shared__ __align__(16) float sxs[8][3][PT];       // 12KB
    __shared__ __align__(16) ull swd[8 * 3 * 64];       // 12KB, [cc*192 + dt*64 + ch] dup pairs

    int tid = threadIdx.x;
    int p0 = blockIdx.x * PT;
    int t = blockIdx.y, b = blockIdx.z;

    for (int i = tid; i < 3 * PT; i += 256) {
        int dt = i / PT, p = i % PT;
        int tin = t + dt - 1;
        float g = 0.f;
        if (tin >= 0 && tin < T_ && p0 + p < HW_)
            g = g_gate[(size_t)(b * T_ + tin) * HW_ + p0 + p];
        sgate[dt][p] = g;
    }

    int ty = tid >> 4, tx = tid & 15;
    int chb = ty * 4, pb = tx * 8;
    ull acc[4][4];
#pragma unroll
    for (int i = 0; i < 4; i++)
#pragma unroll
        for (int j = 0; j < 4; j++) acc[i][j] = 0ULL;

    const float* xb = x + (size_t)b * T_ * C_ * HW_;

    float4 xf[3];
    float wf[6];
    // decode per-thread staging slots (fixed for whole kernel)
    int xcc[3], xdt[3], xp4[3], xok[3];
#pragma unroll
    for (int k = 0; k < 3; k++) {
        int i = tid + k * 256;            // i < 768
        xcc[k] = i / 96;
        int r = i % 96;
        xdt[k] = r / 32;
        xp4[k] = (r & 31) << 2;
        int tin = t + xdt[k] - 1;
        xok[k] = (tin >= 0 && tin < T_ && p0 + xp4[k] < HW_) ? tin : -1;
    }

    // prologue fetch c0 = 0
#pragma unroll
    for (int k = 0; k < 3; k++) {
        xf[k] = make_float4(0.f, 0.f, 0.f, 0.f);
        if (xok[k] >= 0)
            xf[k] = *(const float4*)(xb + ((size_t)(xok[k] * C_ + xcc[k])) * HW_ + p0 + xp4[k]);
    }
#pragma unroll
    for (int k = 0; k < 6; k++) {
        int i = tid + k * 256;            // i < 1536
        wf[k] = g_wr[(i / 192) * 192 + (i % 192)];
    }

    for (int c0 = 0; c0 < C_; c0 += 8) {
        __syncthreads();
        // store staged regs -> smem (apply gate)
#pragma unroll
        for (int k = 0; k < 3; k++) {
            float4 v = xf[k];
            float4 g = *(const float4*)&sgate[xdt[k]][xp4[k]];
            v.x *= g.x; v.y *= g.y; v.z *= g.z; v.w *= g.w;
            *(float4*)&sxs[xcc[k]][xdt[k]][xp4[k]] = v;
        }
#pragma unroll
        for (int k = 0; k < 6; k++)
            swd[tid + k * 256] = packdup(wf[k]);
        __syncthreads();

        // prefetch next chunk
        if (c0 + 8 < C_) {
#pragma unroll
            for (int k = 0; k < 3; k++) {
                xf[k] = make_float4(0.f, 0.f, 0.f, 0.f);
                if (xok[k] >= 0)
                    xf[k] = *(const float4*)(xb + ((size_t)(xok[k] * C_ + c0 + 8 + xcc[k])) * HW_ + p0 + xp4[k]);
            }
#pragma unroll
            for (int k = 0; k < 6; k++) {
                int i = tid + k * 256;
                wf[k] = g_wr[(c0 + 8 + i / 192) * 192 + (i % 192)];
            }
        }

        // compute
#pragma unroll
        for (int cc = 0; cc < 8; cc++) {
#pragma unroll
            for (int dt = 0; dt < 3; dt++) {
                ulonglong2 wA = *(const ulonglong2*)&swd[cc * 192 + dt * 64 + chb];
                ulonglong2 wB = *(const ulonglong2*)&swd[cc * 192 + dt * 64 + chb + 2];
                ulonglong2 xA = *(const ulonglong2*)(const void*)&sxs[cc][dt][pb];
                ulonglong2 xB = *(const ulonglong2*)(const void*)&sxs[cc][dt][pb + 4];
                ull wv[4] = {wA.x, wA.y, wB.x, wB.y};
                ull xv[4] = {xA.x, xA.y, xB.x, xB.y};
#pragma unroll
                for (int i = 0; i < 4; i++)
#pragma unroll
                    for (int j = 0; j < 4; j++)
                        ffma2(acc[i][j], wv[i], xv[j]);
            }
        }
    }

    // BN + relu epilogue
    if (p0 + pb < HW_) {
#pragma unroll
        for (int i = 0; i < 4; i++) {
            int ch = chb + i;
            float inv = gamma[ch] * rsqrtf(var[ch] + 1e-5f);
            float bia = beta[ch] - mean[ch] * inv;
            float* dst = g_t + ((size_t)((b * CH_ + ch) * T_ + t)) * HW_ + p0 + pb;
#pragma unroll
            for (int j = 0; j < 4; j++) {
                float2 f = unpk(acc[i][j]);
                float2 o;
                o.x = fmaxf(fmaf(f.x, inv, bia), 0.f);
                o.y = fmaxf(fmaf(f.y, inv, bia), 0.f);
                *(float2*)(dst + 2 * j) = o;
            }
        }
    }
}

// ---------------- expand 1x1x1 GEMM (256 x PT, K=64) + sigmoid + x_t + v partials ----------------
// 256 thr = 16(ty)x16(tx); chunks of 32 couts, thread tile 2cout x 8px.
__global__ __launch_bounds__(256, 2) void k_expand(const float* __restrict__ x) {
    __shared__ __align__(16) float st[CH_][PT];         // 32KB
    __shared__ __align__(16) ull sw2[CH_ * 32];         // 16KB  [cin*32 + cl] dup pairs

    int tid = threadIdx.x;
    int p0 = blockIdx.x * PT;
    int t = blockIdx.y, b = blockIdx.z;
    int ty = tid >> 4, tx = tid & 15;
    int pb = tx * 8;
    bool pvalid = (p0 + pb < HW_);

    // stage t-buffer tile
    const float* tsrc = g_t + ((size_t)(b * CH_ * T_ + t)) * HW_;
#pragma unroll
    for (int k = 0; k < 8; k++) {
        int i = tid + k * 256;            // i < 2048 float4 slots
        int cin = i >> 5, p4 = (i & 31) << 2;
        float4 v = make_float4(0.f, 0.f, 0.f, 0.f);
        if (p0 + p4 < HW_)
            v = *(const float4*)(tsrc + (size_t)cin * T_ * HW_ + p0 + p4);
        *(float4*)&st[cin][p4] = v;
    }

    // gate (per-px, shared across couts) into regs
    float gt[8];
    if (pvalid) {
        const float* gp = g_gate + (size_t)(b * T_ + t) * HW_ + p0 + pb;
        float4 a = *(const float4*)gp, c = *(const float4*)(gp + 4);
        gt[0] = a.x; gt[1] = a.y; gt[2] = a.z; gt[3] = a.w;
        gt[4] = c.x; gt[5] = c.y; gt[6] = c.z; gt[7] = c.w;
    } else {
#pragma unroll
        for (int k = 0; k < 8; k++) gt[k] = 0.f;
    }

    int lane = tid & 31;

    for (int co = 0; co < 8; co++) {
        __syncthreads();   // covers st on first iter; protects sw2 reuse after
#pragma unroll
        for (int k = 0; k < 8; k++) {
            int i = tid + k * 256;        // i < 2048
            int cin = i >> 5, cl = i & 31;
            sw2[i] = packdup(g_we[cin * C_ + co * 32 + cl]);
        }
        __syncthreads();

        ull acc[2][4];
#pragma unroll
        for (int i = 0; i < 2; i++)
#pragma unroll
            for (int j = 0; j < 4; j++) acc[i][j] = 0ULL;

#pragma unroll 8
        for (int cin = 0; cin < CH_; cin++) {
            ulonglong2 w = *(const ulonglong2*)&sw2[cin * 32 + ty * 2];
            ulonglong2 xA = *(const ulonglong2*)(const void*)&st[cin][pb];
            ulonglong2 xB = *(const ulonglong2*)(const void*)&st[cin][pb + 4];
            ull xv[4] = {xA.x, xA.y, xB.x, xB.y};
#pragma unroll
            for (int j = 0; j < 4; j++) {
                ffma2(acc[0][j], w.x, xv[j]);
                ffma2(acc[1][j], w.y, xv[j]);
            }
        }

        // epilogue: x_t = x*gate*(1+sigmoid(acc)), write + partial sums
        float psum[2];
#pragma unroll
        for (int i = 0; i < 2; i++) {
            int cout = co * 32 + ty * 2 + i;
            float s = 0.f;
            if (pvalid) {
                const float* xsrc = x + ((size_t)((b * T_ + t) * C_ + cout)) * HW_ + p0 + pb;
                float* dst = g_xt + ((size_t)((b * C_ + cout) * T_ + t)) * HW_ + p0 + pb;
                float4 xa = *(const float4*)xsrc, xc = *(const float4*)(xsrc + 4);
                float xin[8] = {xa.x, xa.y, xa.z, xa.w, xc.x, xc.y, xc.z, xc.w};
                float o[8];
#pragma unroll
                for (int j = 0; j < 4; j++) {
                    float2 f = unpk(acc[i][j]);
                    float a0 = 1.f / (1.f + __expf(-f.x));
                    float a1 = 1.f / (1.f + __expf(-f.y));
                    o[2 * j]     = xin[2 * j] * gt[2 * j] * (1.f + a0);
                    o[2 * j + 1] = xin[2 * j + 1] * gt[2 * j + 1] * (1.f + a1);
                    s += o[2 * j] + o[2 * j + 1];
                }
                *(float4*)dst = make_float4(o[0], o[1], o[2], o[3]);
                *(float4*)(dst + 4) = make_float4(o[4], o[5], o[6], o[7]);
            }
            psum[i] = s;
        }
        // shuffle-reduce over the 16 tx lanes in each half-warp
#pragma unroll
        for (int i = 0; i < 2; i++) {
#pragma unroll
            for (int m = 1; m < 16; m <<= 1)
                psum[i] += __shfl_xor_sync(0xffffffffu, psum[i], m);
        }
        if ((lane & 15) == 0) {
#pragma unroll
            for (int i = 0; i < 2; i++) {
                int cout = co * 32 + ty * 2 + i;
                g_vpart[((size_t)((b * C_ + cout) * T_ + t)) * NPB + blockIdx.x] = psum[i];
            }
        }
    }
}

// ---------------- dynamic temporal kernel ----------------
__global__ __launch_bounds__(256) void k_dyn(
    const float* __restrict__ wfc1, const float* __restrict__ bfc1,
    const float* __restrict__ wfc2, const float* __restrict__ bfc2) {
    int id = blockIdx.x * blockDim.x + threadIdx.x;
    if (id >= B_ * C_) return;
    float v[T_];
#pragma unroll
    for (int t = 0; t < T_; t++) {
        const float* pp = g_vpart + ((size_t)id * T_ + t) * NPB;
        float s = 0.f;
#pragma unroll
        for (int k = 0; k < NPB; k++) s += pp[k];
        v[t] = s * (1.f / HW_);
    }
    float lg[3] = {bfc2[0], bfc2[1], bfc2[2]};
#pragma unroll
    for (int hh = 0; hh < 16; hh++) {
        float s = bfc1[hh];
#pragma unroll
        for (int t = 0; t < T_; t++) s += wfc1[hh * 8 + t] * v[t];
        s = fmaxf(s, 0.f);
#pragma unroll
        for (int k = 0; k < 3; k++) lg[k] += wfc2[k * 16 + hh] * s;
    }
    float m = fmaxf(lg[0], fmaxf(lg[1], lg[2]));
    float e0 = __expf(lg[0] - m), e1 = __expf(lg[1] - m), e2 = __expf(lg[2] - m);
    float inv = 1.f / (e0 + e1 + e2);
    g_kern[id * 3 + 0] = e0 * inv;
    g_kern[id * 3 + 1] = e1 * inv;
    g_kern[id * 3 + 2] = e2 * inv;
}

// ---------------- depthwise temporal stencil ----------------
__global__ __launch_bounds__(256) void k_stencil(float* __restrict__ out) {
    int p = blockIdx.x * blockDim.x + threadIdx.x;
    if (p >= HW_) return;
    int bc = blockIdx.y;
    int b = bc >> 8, c = bc & 255;
    float k0 = g_kern[bc * 3 + 0];
    float k1 = g_kern[bc * 3 + 1];
    float k2 = g_kern[bc * 3 + 2];
    const float* src = g_xt + (size_t)bc * T_ * HW_ + p;
    float prev = 0.f, cur = src[0];
#pragma unroll
    for (int t = 0; t < T_; t++) {
        float nxt = (t < T_ - 1) ? src[(size_t)(t + 1) * HW_] : 0.f;
        out[((size_t)((b * T_ + t) * C_ + c)) * HW_ + p] = k0 * prev + k1 * cur + k2 * nxt;
        prev = cur;
        cur = nxt;
    }
}

// ---------------- launch ----------------
extern "C" void kernel_launch(void* const* d_in, const int* in_sizes, int n_in,
                              void* d_out, int out_size) {
    const float* x      = (const float*)d_in[0];
    const float* w_sp   = (const float*)d_in[1];
    const float* w_red  = (const float*)d_in[2];
    const float* gam    = (const float*)d_in[3];
    const float* bet    = (const float*)d_in[4];
    const float* mea    = (const float*)d_in[5];
    const float* var    = (const float*)d_in[6];
    const float* w_exp  = (const float*)d_in[7];
    const float* wfc1   = (const float*)d_in[8];
    const float* bfc1   = (const float*)d_in[9];
    const float* wfc2   = (const float*)d_in[10];
    const float* bfc2   = (const float*)d_in[11];
    float* out = (float*)d_out;

    k_prep<<<192, 256>>>(w_red, w_exp);
    k_maxmean<<<dim3(13, B_ * T_), 256>>>(x);
    k_spatial<<<dim3(13, B_ * T_), 256>>>(w_sp);
    k_reduce<<<dim3(NPB, T_, B_), 256>>>(x, gam, bet, mea, var);
    k_expand<<<dim3(NPB, T_, B_), 256>>>(x);
    k_dyn<<<8, 256>>>(wfc1, bfc1, wfc2, bfc2);
    k_stencil<<<dim3(13, B_ * C_), 256>>>(out);
}

// round 3
// speedup vs baseline: 1.5438x; 1.5438x over previous
#include <cuda_runtime.h>
#include <math.h>

#define B_    8
#define T_    8
#define C_    256
#define CH_   64
#define Wd    56
#define HW_   3136
#define PT    128
#define NPB   25          // ceil(HW_/PT)

typedef unsigned long long ull;

// ---------------- scratch (device globals) ----------------
__device__ float g_maxavg[(size_t)B_ * T_ * 2 * HW_];
__device__ float g_gate[(size_t)B_ * T_ * HW_];
__device__ float g_wr[C_ * 3 * CH_];                    // [c*192 + dt*64 + ch]
__device__ float g_we[CH_ * C_];                        // [cin*256 + cout]
__device__ float g_t[(size_t)B_ * CH_ * T_ * HW_];      // (B,64,T,HW)
__device__ float g_xt[(size_t)B_ * C_ * T_ * HW_];      // (B,C,T,HW)
__device__ float g_vpart[(size_t)B_ * C_ * T_ * NPB];
__device__ float g_kern[B_ * C_ * 3];

// ---------------- f32x2 helpers ----------------
__device__ __forceinline__ void ffma2(ull& d, ull a, ull b) {
    asm("fma.rn.f32x2 %0, %1, %2, %0;" : "+l"(d) : "l"(a), "l"(b));
}
__device__ __forceinline__ ull packdup(float w) {
    ull u; asm("mov.b64 %0, {%1, %1};" : "=l"(u) : "f"(w)); return u;
}
__device__ __forceinline__ float2 unpk(ull u) {
    float2 f; asm("mov.b64 {%0, %1}, %2;" : "=f"(f.x), "=f"(f.y) : "l"(u)); return f;
}

// ---------------- prep: transpose weights ----------------
__global__ void k_prep(const float* __restrict__ wr, const float* __restrict__ we) {
    int idx = blockIdx.x * blockDim.x + threadIdx.x;
    if (idx < C_ * 3 * CH_) {
        int ch = idx & 63;
        int dtc = idx >> 6;
        int c = dtc / 3, dt = dtc % 3;
        g_wr[idx] = wr[ch * (C_ * 3) + c * 3 + dt];
    }
    if (idx < CH_ * C_) {
        int cout = idx & 255;
        int cin = idx >> 8;
        g_we[idx] = we[cout * CH_ + cin];
    }
}

// ---------------- channel max/mean ----------------
__global__ __launch_bounds__(256) void k_maxmean(const float* __restrict__ x) {
    int bt = blockIdx.y;
    int p = blockIdx.x * blockDim.x + threadIdx.x;
    if (p >= HW_) return;
    const float* xp = x + (size_t)bt * C_ * HW_ + p;
    float mx = -INFINITY, sm = 0.f;
#pragma unroll 4
    for (int c = 0; c < C_; c++) {
        float v = xp[(size_t)c * HW_];
        mx = fmaxf(mx, v);
        sm += v;
    }
    g_maxavg[(size_t)bt * 2 * HW_ + p] = mx;
    g_maxavg[(size_t)bt * 2 * HW_ + HW_ + p] = sm * (1.f / C_);
}

// ---------------- 7x7 conv -> spatial gate ----------------
__global__ __launch_bounds__(256) void k_spatial(const float* __restrict__ w) {
    __shared__ float sw[98];
    int tid = threadIdx.x;
    if (tid < 98) sw[tid] = w[tid];
    __syncthreads();
    int bt = blockIdx.y;
    int p = blockIdx.x * blockDim.x + tid;
    if (p >= HW_) return;
    int py = p / Wd, px = p % Wd;
    const float* mb = g_maxavg + (size_t)bt * 2 * HW_;
    float s = 0.f;
#pragma unroll
    for (int ky = 0; ky < 7; ky++) {
        int iy = py + ky - 3;
        if (iy < 0 || iy >= Wd) continue;
#pragma unroll
        for (int kx = 0; kx < 7; kx++) {
            int ix = px + kx - 3;
            if (ix < 0 || ix >= Wd) continue;
            float m = mb[iy * Wd + ix];
            float a = mb[HW_ + iy * Wd + ix];
            s += sw[ky * 7 + kx] * m + sw[49 + ky * 7 + kx] * a;
        }
    }
    g_gate[(size_t)bt * HW_ + p] = 1.f + 1.f / (1.f + __expf(-s));
}

// ---------------- fused gated reduce conv3d GEMM (64 x 128, K=768) + BN + relu ----------------
// 8 warps split 128 px (16 each). Lane = 8(chg) x 4(pxg); lane tile 8ch x 4px.
__global__ __launch_bounds__(256, 2) void k_reduce(
    const float* __restrict__ x, const float* __restrict__ gamma,
    const float* __restrict__ beta, const float* __restrict__ mean,
    const float* __restrict__ var) {
    __shared__ __align__(16) float sgate[3][PT];
    __shared__ __align__(16) float sxs[8][3][PT];       // 12KB
    __shared__ __align__(16) float swi[8 * 192];        // 6KB interleaved

    int tid = threadIdx.x;
    int p0 = blockIdx.x * PT;
    int t = blockIdx.y, b = blockIdx.z;

    for (int i = tid; i < 3 * PT; i += 256) {
        int dt = i / PT, p = i % PT;
        int tin = t + dt - 1;
        float g = 0.f;
        if (tin >= 0 && tin < T_ && p0 + p < HW_)
            g = g_gate[(size_t)(b * T_ + tin) * HW_ + p0 + p];
        sgate[dt][p] = g;
    }

    int warp = tid >> 5, lane = tid & 31;
    int chg = lane & 7, pxg = lane >> 3;
    int pxb = warp * 16 + pxg * 4;

    ull acc[8][2];
#pragma unroll
    for (int i = 0; i < 8; i++) { acc[i][0] = 0ULL; acc[i][1] = 0ULL; }

    const float* xb = x + (size_t)b * T_ * C_ * HW_;

    float4 xf[3];
    float wf[6];
    int xcc[3], xdt[3], xp4[3], xok[3];
#pragma unroll
    for (int k = 0; k < 3; k++) {
        int i = tid + k * 256;            // < 768
        xcc[k] = i / 96;
        int r = i % 96;
        xdt[k] = r / 32;
        xp4[k] = (r & 31) << 2;
        int tin = t + xdt[k] - 1;
        xok[k] = (tin >= 0 && tin < T_ && p0 + xp4[k] < HW_) ? tin : -1;
    }
    int wcc[6], wsrc[6];
#pragma unroll
    for (int k = 0; k < 6; k++) {
        int o = tid + k * 256;            // < 1536
        wcc[k] = o / 192;
        int r = o % 192;
        int dt = r >> 6, q = r & 63;
        int half = q >> 5, cg = (q >> 2) & 7, ii = q & 3;
        wsrc[k] = dt * 64 + cg * 8 + half * 4 + ii;   // offset within a c-slice of g_wr
    }

    // prologue fetch c0 = 0
#pragma unroll
    for (int k = 0; k < 3; k++) {
        xf[k] = make_float4(0.f, 0.f, 0.f, 0.f);
        if (xok[k] >= 0)
            xf[k] = *(const float4*)(xb + ((size_t)(xok[k] * C_ + xcc[k])) * HW_ + p0 + xp4[k]);
    }
#pragma unroll
    for (int k = 0; k < 6; k++)
        wf[k] = g_wr[wcc[k] * 192 + wsrc[k]];

    for (int c0 = 0; c0 < C_; c0 += 8) {
        __syncthreads();
#pragma unroll
        for (int k = 0; k < 3; k++) {
            float4 v = xf[k];
            float4 g = *(const float4*)&sgate[xdt[k]][xp4[k]];
            v.x *= g.x; v.y *= g.y; v.z *= g.z; v.w *= g.w;
            *(float4*)&sxs[xcc[k]][xdt[k]][xp4[k]] = v;
        }
#pragma unroll
        for (int k = 0; k < 6; k++)
            swi[tid + k * 256] = wf[k];
        __syncthreads();

        if (c0 + 8 < C_) {
#pragma unroll
            for (int k = 0; k < 3; k++) {
                xf[k] = make_float4(0.f, 0.f, 0.f, 0.f);
                if (xok[k] >= 0)
                    xf[k] = *(const float4*)(xb + ((size_t)(xok[k] * C_ + c0 + 8 + xcc[k])) * HW_ + p0 + xp4[k]);
            }
#pragma unroll
            for (int k = 0; k < 6; k++)
                wf[k] = g_wr[(c0 + 8 + wcc[k]) * 192 + wsrc[k]];
        }

#pragma unroll
        for (int cc = 0; cc < 8; cc++) {
#pragma unroll
            for (int dt = 0; dt < 3; dt++) {
                const float* wrow = &swi[cc * 192 + dt * 64];
                float4 wlo = *(const float4*)(wrow + chg * 4);
                float4 whi = *(const float4*)(wrow + 32 + chg * 4);
                ull wd[8];
                wd[0] = packdup(wlo.x); wd[1] = packdup(wlo.y);
                wd[2] = packdup(wlo.z); wd[3] = packdup(wlo.w);
                wd[4] = packdup(whi.x); wd[5] = packdup(whi.y);
                wd[6] = packdup(whi.z); wd[7] = packdup(whi.w);
                ulonglong2 xv = *(const ulonglong2*)(const void*)&sxs[cc][dt][pxb];
#pragma unroll
                for (int j = 0; j < 8; j++) {
                    ffma2(acc[j][0], wd[j], xv.x);
                    ffma2(acc[j][1], wd[j], xv.y);
                }
            }
        }
    }

    // BN + relu epilogue: lane writes 8ch x 4px
    if (p0 + pxb < HW_) {
#pragma unroll
        for (int j = 0; j < 8; j++) {
            int ch = chg * 8 + j;
            float inv = gamma[ch] * rsqrtf(var[ch] + 1e-5f);
            float bia = beta[ch] - mean[ch] * inv;
            float2 f0 = unpk(acc[j][0]);
            float2 f1 = unpk(acc[j][1]);
            float4 o;
            o.x = fmaxf(fmaf(f0.x, inv, bia), 0.f);
            o.y = fmaxf(fmaf(f0.y, inv, bia), 0.f);
            o.z = fmaxf(fmaf(f1.x, inv, bia), 0.f);
            o.w = fmaxf(fmaf(f1.y, inv, bia), 0.f);
            *(float4*)(g_t + ((size_t)((b * CH_ + ch) * T_ + t)) * HW_ + p0 + pxb) = o;
        }
    }
}

// ---------------- expand 1x1x1 GEMM (256 x 128, K=64) + sigmoid + x_t + v partials ----------------
// 4 chunks of 64 couts; lane tile 8co x 4px, lanes 8(cog) x 4(pxg), 8 warps split px.
__global__ __launch_bounds__(256, 2) void k_expand(const float* __restrict__ x) {
    __shared__ __align__(16) float st[CH_][PT];         // 32KB
    __shared__ __align__(16) float swi2[CH_ * 64];      // 16KB interleaved
    __shared__ float sred[8][64];                       // 2KB

    int tid = threadIdx.x;
    int p0 = blockIdx.x * PT;
    int t = blockIdx.y, b = blockIdx.z;
    int warp = tid >> 5, lane = tid & 31;
    int cog = lane & 7, pxg = lane >> 3;
    int pxb = warp * 16 + pxg * 4;
    bool pv = (p0 + pxb < HW_);

    // stage t-buffer tile
    const float* tsrc = g_t + ((size_t)(b * CH_ * T_ + t)) * HW_;
#pragma unroll
    for (int k = 0; k < 8; k++) {
        int i = tid + k * 256;            // < 2048 float4 slots
        int cin = i >> 5, p4 = (i & 31) << 2;
        float4 v = make_float4(0.f, 0.f, 0.f, 0.f);
        if (p0 + p4 < HW_)
            v = *(const float4*)(tsrc + (size_t)cin * T_ * HW_ + p0 + p4);
        *(float4*)&st[cin][p4] = v;
    }

    float4 gv = make_float4(0.f, 0.f, 0.f, 0.f);
    if (pv) gv = *(const float4*)(g_gate + (size_t)(b * T_ + t) * HW_ + p0 + pxb);

    for (int chunk = 0; chunk < 4; chunk++) {
        int co0 = chunk * 64;
        __syncthreads();   // covers st (chunk0), protects swi2/sred reuse
#pragma unroll
        for (int k = 0; k < 16; k++) {
            int o = tid + k * 256;        // < 4096
            int cin = o >> 6, q = o & 63;
            int half = q >> 5, cg = (q >> 2) & 7, ii = q & 3;
            swi2[o] = g_we[cin * C_ + co0 + cg * 8 + half * 4 + ii];
        }
        __syncthreads();

        ull acc[8][2];
#pragma unroll
        for (int i = 0; i < 8; i++) { acc[i][0] = 0ULL; acc[i][1] = 0ULL; }

#pragma unroll 8
        for (int cin = 0; cin < CH_; cin++) {
            const float* wrow = &swi2[cin * 64];
            float4 wlo = *(const float4*)(wrow + cog * 4);
            float4 whi = *(const float4*)(wrow + 32 + cog * 4);
            ull wd[8];
            wd[0] = packdup(wlo.x); wd[1] = packdup(wlo.y);
            wd[2] = packdup(wlo.z); wd[3] = packdup(wlo.w);
            wd[4] = packdup(whi.x); wd[5] = packdup(whi.y);
            wd[6] = packdup(whi.z); wd[7] = packdup(whi.w);
            ulonglong2 xv = *(const ulonglong2*)(const void*)&st[cin][pxb];
#pragma unroll
            for (int j = 0; j < 8; j++) {
                ffma2(acc[j][0], wd[j], xv.x);
                ffma2(acc[j][1], wd[j], xv.y);
            }
        }

        // epilogue: x_t = x*gate*(1+sigmoid(acc))
        float psum[8];
#pragma unroll
        for (int j = 0; j < 8; j++) {
            psum[j] = 0.f;
            if (pv) {
                int co = co0 + cog * 8 + j;
                float4 xin = *(const float4*)(x + ((size_t)((b * T_ + t) * C_ + co)) * HW_ + p0 + pxb);
                float2 f0 = unpk(acc[j][0]);
                float2 f1 = unpk(acc[j][1]);
                float4 o;
                o.x = xin.x * gv.x * (2.f - 1.f / (1.f + __expf(f0.x)));
                o.y = xin.y * gv.y * (2.f - 1.f / (1.f + __expf(f0.y)));
                o.z = xin.z * gv.z * (2.f - 1.f / (1.f + __expf(f1.x)));
                o.w = xin.w * gv.w * (2.f - 1.f / (1.f + __expf(f1.y)));
                // note: 1 + sigmoid(s) = 2 - 1/(1+e^s)
                *(float4*)(g_xt + ((size_t)((b * C_ + co) * T_ + t)) * HW_ + p0 + pxb) = o;
                psum[j] = o.x + o.y + o.z + o.w;
            }
        }
#pragma unroll
        for (int j = 0; j < 8; j++) {
            psum[j] += __shfl_xor_sync(0xffffffffu, psum[j], 8);
            psum[j] += __shfl_xor_sync(0xffffffffu, psum[j], 16);
        }
        if (pxg == 0) {
#pragma unroll
            for (int j = 0; j < 8; j++)
                sred[warp][cog * 8 + j] = psum[j];
        }
        __syncthreads();
        if (tid < 64) {
            float s = 0.f;
#pragma unroll
            for (int w = 0; w < 8; w++) s += sred[w][tid];
            g_vpart[((size_t)((b * C_ + co0 + tid) * T_ + t)) * NPB + blockIdx.x] = s;
        }
    }
}

// ---------------- dynamic temporal kernel ----------------
__global__ __launch_bounds__(256) void k_dyn(
    const float* __restrict__ wfc1, const float* __restrict__ bfc1,
    const float* __restrict__ wfc2, const float* __restrict__ bfc2) {
    int id = blockIdx.x * blockDim.x + threadIdx.x;
    if (id >= B_ * C_) return;
    float v[T_];
#pragma unroll
    for (int t = 0; t < T_; t++) {
        const float* pp = g_vpart + ((size_t)id * T_ + t) * NPB;
        float s = 0.f;
#pragma unroll
        for (int k = 0; k < NPB; k++) s += pp[k];
        v[t] = s * (1.f / HW_);
    }
    float lg[3] = {bfc2[0], bfc2[1], bfc2[2]};
#pragma unroll
    for (int hh = 0; hh < 16; hh++) {
        float s = bfc1[hh];
#pragma unroll
        for (int t = 0; t < T_; t++) s += wfc1[hh * 8 + t] * v[t];
        s = fmaxf(s, 0.f);
#pragma unroll
        for (int k = 0; k < 3; k++) lg[k] += wfc2[k * 16 + hh] * s;
    }
    float m = fmaxf(lg[0], fmaxf(lg[1], lg[2]));
    float e0 = __expf(lg[0] - m), e1 = __expf(lg[1] - m), e2 = __expf(lg[2] - m);
    float inv = 1.f / (e0 + e1 + e2);
    g_kern[id * 3 + 0] = e0 * inv;
    g_kern[id * 3 + 1] = e1 * inv;
    g_kern[id * 3 + 2] = e2 * inv;
}

// ---------------- depthwise temporal stencil ----------------
__global__ __launch_bounds__(256) void k_stencil(float* __restrict__ out) {
    int p = blockIdx.x * blockDim.x + threadIdx.x;
    if (p >= HW_) return;
    int bc = blockIdx.y;
    int b = bc >> 8, c = bc & 255;
    float k0 = g_kern[bc * 3 + 0];
    float k1 = g_kern[bc * 3 + 1];
    float k2 = g_kern[bc * 3 + 2];
    const float* src = g_xt + (size_t)bc * T_ * HW_ + p;
    float prev = 0.f, cur = src[0];
#pragma unroll
    for (int t = 0; t < T_; t++) {
        float nxt = (t < T_ - 1) ? src[(size_t)(t + 1) * HW_] : 0.f;
        out[((size_t)((b * T_ + t) * C_ + c)) * HW_ + p] = k0 * prev + k1 * cur + k2 * nxt;
        prev = cur;
        cur = nxt;
    }
}

// ---------------- launch ----------------
extern "C" void kernel_launch(void* const* d_in, const int* in_sizes, int n_in,
                              void* d_out, int out_size) {
    const float* x      = (const float*)d_in[0];
    const float* w_sp   = (const float*)d_in[1];
    const float* w_red  = (const float*)d_in[2];
    const float* gam    = (const float*)d_in[3];
    const float* bet    = (const float*)d_in[4];
    const float* mea    = (const float*)d_in[5];
    const float* var    = (const float*)d_in[6];
    const float* w_exp  = (const float*)d_in[7];
    const float* wfc1   = (const float*)d_in[8];
    const float* bfc1   = (const float*)d_in[9];
    const float* wfc2   = (const float*)d_in[10];
    const float* bfc2   = (const float*)d_in[11];
    float* out = (float*)d_out;

    k_prep<<<192, 256>>>(w_red, w_exp);
    k_maxmean<<<dim3(13, B_ * T_), 256>>>(x);
    k_spatial<<<dim3(13, B_ * T_), 256>>>(w_sp);
    k_reduce<<<dim3(NPB, T_, B_), 256>>>(x, gam, bet, mea, var);
    k_expand<<<dim3(NPB, T_, B_), 256>>>(x);
    k_dyn<<<8, 256>>>(wfc1, bfc1, wfc2, bfc2);
    k_stencil<<<dim3(13, B_ * C_), 256>>>(out);
}